// round 2
// baseline (speedup 1.0000x reference)
#include <cuda_runtime.h>

// ---------------- problem constants ----------------
#define WSZ 21                  // window_size
#define KK  43                  // 2*WSZ+1
#define HH  128
#define WW  128
#define BB  2
#define CC  3
#define SIG_COLOR 50.0f         // 1/(0.1^2 * 2)
#define SIG_SPACE (1.0f/98.0f)  // 1/(7^2 * 2)
#define LPOW 0.8f
#define C1T 20.0f
#define C2T 10.0f

// ---------------- tiling ----------------
#define TX 32
#define TY 8
#define PITCH (TX + 2*WSZ)      // 74
#define ROWSM (TY + 2*WSZ)      // 50
#define PLANE (ROWSM*PITCH)     // 3700
#define NTHREADS 256
#define NSPLIT 7                // dy chunks -> grid 896 CTAs ~ 3 waves @ occ 2
#define GXD (WW/TX)             // 4
#define GYD (HH/TY)             // 16
#define NPART (GXD*GYD*BB*NSPLIT)   // 896

// ---------------- scratch (no allocation allowed) ----------------
__device__ float  g_mask[BB*HH*WW];
__device__ double g_part[NPART];

__device__ __forceinline__ int refl(int i, int n) {
    // jnp.pad 'reflect' (mirror without edge duplication); max overhang is WSZ < n
    if (i < 0)  i = -i;
    if (i >= n) i = 2*n - 2 - i;
    return i;
}

// |d|^0.8 via explicit lg2/ex2 (2 MUFU). lg2(0) = -inf -> ex2 -> 0, matching safe_pow.
__device__ __forceinline__ float pow08(float d) {
    return exp2f(LPOW * __log2f(fabsf(d)));
}

// ================= prepass: edge response + mask =================
__global__ void edge_mask_kernel(const float* __restrict__ orig,
                                 const float* __restrict__ smth) {
    int idx = blockIdx.x * blockDim.x + threadIdx.x;
    if (idx >= BB*HH*WW) return;
    int w = idx % WW;
    int h = (idx / WW) % HH;
    int b = idx / (HH*WW);

    float eo = 0.f, es = 0.f;
#pragma unroll
    for (int c = 0; c < CC; c++) {
        const float* po = orig + ((size_t)(b*CC + c))*HH*WW;
        const float* ps = smth + ((size_t)(b*CC + c))*HH*WW;
        float vo[3][3], vs[3][3];
#pragma unroll
        for (int u = 0; u < 3; u++) {
            int hh = refl(h + u - 1, HH);
#pragma unroll
            for (int v = 0; v < 3; v++) {
                int ww = refl(w + v - 1, WW);
                vo[u][v] = po[hh*WW + ww];
                vs[u][v] = ps[hh*WW + ww];
            }
        }
        float gxo = (vo[0][2]-vo[0][0]) + 2.f*(vo[1][2]-vo[1][0]) + (vo[2][2]-vo[2][0]);
        float gyo = (vo[2][0]-vo[0][0]) + 2.f*(vo[2][1]-vo[0][1]) + (vo[2][2]-vo[0][2]);
        eo += sqrtf(gxo*gxo + gyo*gyo);
        float gxs = (vs[0][2]-vs[0][0]) + 2.f*(vs[1][2]-vs[1][0]) + (vs[2][2]-vs[2][0]);
        float gys = (vs[2][0]-vs[0][0]) + 2.f*(vs[2][1]-vs[0][1]) + (vs[2][2]-vs[0][2]);
        es += sqrtf(gxs*gxs + gys*gys);
    }
    g_mask[idx] = ((eo < C1T) && (es - eo > C2T)) ? 1.0f : 0.0f;
}

// ================= main: windowed loss =================
__global__ void __launch_bounds__(NTHREADS, 2)
loss_kernel(const float* __restrict__ orig, const float* __restrict__ smth) {
    extern __shared__ float smem[];
    float* S0 = smem;
    float* S1 = smem + PLANE;
    float* S2 = smem + 2*PLANE;
    float* O0 = smem + 3*PLANE;
    float* O1 = smem + 4*PLANE;
    float* O2 = smem + 5*PLANE;

    __shared__ float  wsx[KK];
    __shared__ double wsum[NTHREADS/32];

    const int t  = threadIdx.x;
    const int bz = blockIdx.z;
    const int b  = bz / NSPLIT;
    const int chunk = bz % NSPLIT;

    const int x0 = blockIdx.x * TX - WSZ;
    const int y0 = blockIdx.y * TY - WSZ;

    const size_t cs = (size_t)HH*WW;            // channel stride
    const float* __restrict__ sb = smth + (size_t)b*CC*cs;
    const float* __restrict__ ob = orig + (size_t)b*CC*cs;

    // cooperative load of padded tile, 6 planes
    for (int i = t; i < PLANE; i += NTHREADS) {
        int r = i / PITCH;
        int c = i - r*PITCH;
        int gh = refl(y0 + r, HH);
        int gw = refl(x0 + c, WW);
        int g  = gh*WW + gw;
        S0[i] = sb[g];        S1[i] = sb[g + cs];   S2[i] = sb[g + 2*cs];
        O0[i] = ob[g];        O1[i] = ob[g + cs];   O2[i] = ob[g + 2*cs];
    }
    if (t < KK) {
        float dx = (float)(t - WSZ);
        wsx[t] = __expf(-SIG_SPACE * dx * dx);
    }
    __syncthreads();

    const int tx = t & 31;
    const int ty = t >> 5;

    const int ci = (ty + WSZ)*PITCH + (tx + WSZ);
    const float cs0 = S0[ci], cs1 = S1[ci], cs2 = S2[ci];
    const float co0 = O0[ci], co1 = O1[ci], co2 = O2[ci];

    const int py = blockIdx.y * TY + ty;
    const int px = blockIdx.x * TX + tx;
    const float m = g_mask[(b*HH + py)*WW + px];

    // dy chunk bounds (KK=43 = 7 chunks: one of 7 rows, six of 6)
    const int base = KK / NSPLIT;               // 6
    const int rem  = KK % NSPLIT;               // 1
    const int start = chunk*base + (chunk < rem ? chunk : rem);
    const int cnt   = base + (chunk < rem ? 1 : 0);

    float accA = 0.f;   // sum_dy wy * sum_dx wsx * sum_c d^2
    float accB = 0.f;   // sum wr * sum_c |d|^0.8

    for (int j = 0; j < cnt; j++) {
        const int dy = start + j - WSZ;
        const float wy = __expf(-SIG_SPACE * (float)(dy*dy));
        const int rbase = (ty + WSZ + dy)*PITCH + tx;
        float rowA = 0.f;
#pragma unroll
        for (int dxi = 0; dxi < KK; dxi++) {
            const int ii = rbase + dxi;
            float ss0 = S0[ii], ss1 = S1[ii], ss2 = S2[ii];
            float so0 = O0[ii], so1 = O1[ii], so2 = O2[ii];
            float e0 = co0 - so0, e1 = co1 - so1, e2 = co2 - so2;
            float wr = __expf(-SIG_COLOR * (e0*e0 + e1*e1 + e2*e2));
            float d0 = cs0 - ss0, d1 = cs1 - ss1, d2 = cs2 - ss2;
            float dd = fmaf(d0, d0, fmaf(d1, d1, d2*d2));
            rowA = fmaf(wsx[dxi], dd, rowA);
            float p = pow08(d0) + pow08(d1) + pow08(d2);
            accB = fmaf(wr, p, accB);
        }
        accA = fmaf(wy, rowA, accA);
    }

    float tot = fmaf(m, accA, (1.0f - m)*accB);

    // deterministic block reduction
#pragma unroll
    for (int o = 16; o > 0; o >>= 1)
        tot += __shfl_down_sync(0xffffffffu, tot, o);
    if ((t & 31) == 0) wsum[t >> 5] = (double)tot;
    __syncthreads();
    if (t == 0) {
        double s = 0.0;
#pragma unroll
        for (int i = 0; i < NTHREADS/32; i++) s += wsum[i];
        int bid = blockIdx.x + GXD*(blockIdx.y + GYD*blockIdx.z);
        g_part[bid] = s;
    }
}

// ================= finalize: fixed-order reduce =================
__global__ void finalize_kernel(float* __restrict__ out) {
    __shared__ double sh[1024];
    int t = threadIdx.x;
    sh[t] = (t < NPART) ? g_part[t] : 0.0;
    __syncthreads();
#pragma unroll
    for (int s = 512; s > 0; s >>= 1) {
        if (t < s) sh[t] += sh[t + s];
        __syncthreads();
    }
    if (t == 0) out[0] = (float)(sh[0] / (double)(BB*HH*WW));
}

// ================= launcher =================
extern "C" void kernel_launch(void* const* d_in, const int* in_sizes, int n_in,
                              void* d_out, int out_size) {
    const float* orig = (const float*)d_in[0];   // original_images (2,3,128,128)
    const float* smth = (const float*)d_in[1];   // smooth_images   (2,3,128,128)
    float* out = (float*)d_out;

    const int smem_bytes = 6 * PLANE * (int)sizeof(float);   // 88800 B -> 2 CTAs/SM
    cudaFuncSetAttribute(loss_kernel,
                         cudaFuncAttributeMaxDynamicSharedMemorySize, smem_bytes);

    edge_mask_kernel<<<(BB*HH*WW + 255)/256, 256>>>(orig, smth);
    loss_kernel<<<dim3(GXD, GYD, BB*NSPLIT), NTHREADS, smem_bytes>>>(orig, smth);
    finalize_kernel<<<1, 1024>>>(out);
}

// round 6
// speedup vs baseline: 1.4707x; 1.4707x over previous
#include <cuda_runtime.h>

// ---------------- problem constants ----------------
#define WSZ 21                  // window_size
#define KK  43                  // 2*WSZ+1
#define HH  128
#define WW  128
#define BB  2
#define CC  3
#define SIG_COLOR 50.0f         // 1/(0.1^2 * 2)
#define SIG_SPACE (1.0f/98.0f)  // 1/(7^2 * 2)
#define LPOW 0.8f
#define C1T 20.0f
#define C2T 10.0f
#define LOG2E 1.4426950408889634f

// ---------------- tiling ----------------
#define TX 32
#define TY 8
#define PITCH (TX + 2*WSZ)      // 74
#define ROWSM (TY + 2*WSZ)      // 50
#define PLANE (ROWSM*PITCH)     // 3700
#define NTHREADS 256
#define NSPLIT 6                // dy chunks -> 768 CTAs = 296+296+176 (3 clean waves)
#define GXD (WW/TX)             // 4
#define GYD (HH/TY)             // 16
#define NPART (GXD*GYD*BB*NSPLIT)   // 768

// ---------------- scratch (no allocation allowed) ----------------
__device__ double       g_part[NPART];
__device__ unsigned int g_tick;          // zero-initialized; reset by reducer each call

__device__ __forceinline__ int refl(int i, int n) {
    // jnp.pad 'reflect' (mirror, no edge dup); max overhang WSZ < n
    if (i < 0)  i = -i;
    if (i >= n) i = 2*n - 2 - i;
    return i;
}

// guaranteed single-MUFU lowerings
__device__ __forceinline__ float ex2f(float x) {
    float y; asm("ex2.approx.ftz.f32 %0, %1;" : "=f"(y) : "f"(x)); return y;
}
__device__ __forceinline__ float lg2f(float x) {
    float y; asm("lg2.approx.ftz.f32 %0, %1;" : "=f"(y) : "f"(x)); return y;
}

// ================= single fused kernel =================
__global__ void __launch_bounds__(NTHREADS, 2)
loss_kernel(const float* __restrict__ orig, const float* __restrict__ smth,
            float* __restrict__ out) {
    extern __shared__ float smem[];
    float* S0 = smem;
    float* S1 = smem + PLANE;
    float* S2 = smem + 2*PLANE;
    float* O0 = smem + 3*PLANE;
    float* O1 = smem + 4*PLANE;
    float* O2 = smem + 5*PLANE;

    __shared__ float  wsx[KK];
    __shared__ double wsum[NTHREADS/32];
    __shared__ double red[NTHREADS];
    __shared__ int    s_last;

    const int t  = threadIdx.x;
    const int bz = blockIdx.z;
    const int b  = bz / NSPLIT;
    const int chunk = bz - b*NSPLIT;

    const int x0 = blockIdx.x * TX - WSZ;
    const int y0 = blockIdx.y * TY - WSZ;

    const size_t cs = (size_t)HH*WW;            // channel stride
    const float* __restrict__ sb = smth + (size_t)b*CC*cs;
    const float* __restrict__ ob = orig + (size_t)b*CC*cs;

    // cooperative load of reflect-padded tile, 6 planes
    for (int i = t; i < PLANE; i += NTHREADS) {
        int r = i / PITCH;
        int c = i - r*PITCH;
        int gh = refl(y0 + r, HH);
        int gw = refl(x0 + c, WW);
        int g  = gh*WW + gw;
        S0[i] = sb[g];        S1[i] = sb[g + cs];   S2[i] = sb[g + 2*cs];
        O0[i] = ob[g];        O1[i] = ob[g + cs];   O2[i] = ob[g + 2*cs];
    }
    if (t < KK) {
        float dx = (float)(t - WSZ);
        wsx[t] = ex2f(-SIG_SPACE * LOG2E * dx * dx);
    }
    __syncthreads();

    const int tx = t & 31;
    const int ty = t >> 5;
    const int ci = (ty + WSZ)*PITCH + (tx + WSZ);

    const float cs0 = S0[ci], cs1 = S1[ci], cs2 = S2[ci];
    const float co0 = O0[ci], co1 = O1[ci], co2 = O2[ci];

    // ---- fused mask: Sobel magnitude from SMEM (tile already reflect-padded,
    // so the 3x3 neighborhood equals the reflected-image neighborhood) ----
    float m;
    {
        float eo = 0.f, es = 0.f;
        const float* PL[6] = {O0, O1, O2, S0, S1, S2};
#pragma unroll
        for (int p = 0; p < 6; p++) {
            const float* q = PL[p] + ci;
            float a00 = q[-PITCH-1], a01 = q[-PITCH], a02 = q[-PITCH+1];
            float a10 = q[-1],                        a12 = q[+1];
            float a20 = q[ PITCH-1], a21 = q[ PITCH], a22 = q[ PITCH+1];
            float gx = (a02 - a00) + 2.f*(a12 - a10) + (a22 - a20);
            float gy = (a20 - a00) + 2.f*(a21 - a01) + (a22 - a02);
            float g  = sqrtf(gx*gx + gy*gy);
            if (p < 3) eo += g; else es += g;
        }
        m = ((eo < C1T) && (es - eo > C2T)) ? 1.0f : 0.0f;
    }

    // dy chunk bounds: KK=43 over 6 chunks -> first chunk 8 rows, rest 7
    const int base  = KK / NSPLIT;              // 7
    const int rem   = KK % NSPLIT;              // 1
    const int start = chunk*base + (chunk < rem ? chunk : rem);
    const int cnt   = base + (chunk < rem ? 1 : 0);

    float accA = 0.f;   // sum_dy wy * sum_dx wsx * sum_c d^2
    float accB = 0.f;   // sum ex2(W + 0.8*lg2|dc|)  ==  sum wr * sum_c |d|^0.8

    for (int j = 0; j < cnt; j++) {
        const int dy = start + j - WSZ;
        const float wy = ex2f(-SIG_SPACE * LOG2E * (float)(dy*dy));
        const int rbase = (ty + WSZ + dy)*PITCH + tx;
        float rowA = 0.f;
#pragma unroll
        for (int dxi = 0; dxi < KK; dxi++) {
            const int ii = rbase + dxi;
            float ss0 = S0[ii], ss1 = S1[ii], ss2 = S2[ii];
            float so0 = O0[ii], so1 = O1[ii], so2 = O2[ii];
            float e0 = co0 - so0, e1 = co1 - so1, e2 = co2 - so2;
            float ee = fmaf(e0, e0, fmaf(e1, e1, e2*e2));
            float W  = (-SIG_COLOR * LOG2E) * ee;       // log2 of range weight
            float d0 = cs0 - ss0, d1 = cs1 - ss1, d2 = cs2 - ss2;
            float dd = fmaf(d0, d0, fmaf(d1, d1, d2*d2));
            rowA = fmaf(wsx[dxi], dd, rowA);
            // wr*|dc|^0.8 = ex2(W + 0.8*lg2|dc|);  d==0 -> lg2=-inf -> 0 (safe_pow)
            float p0 = ex2f(fmaf(LPOW, lg2f(fabsf(d0)), W));
            float p1 = ex2f(fmaf(LPOW, lg2f(fabsf(d1)), W));
            float p2 = ex2f(fmaf(LPOW, lg2f(fabsf(d2)), W));
            accB += p0 + p1 + p2;
        }
        accA = fmaf(wy, rowA, accA);
    }

    float tot = fmaf(m, accA, (1.0f - m)*accB);

    // deterministic block reduction
#pragma unroll
    for (int o = 16; o > 0; o >>= 1)
        tot += __shfl_down_sync(0xffffffffu, tot, o);
    if ((t & 31) == 0) wsum[t >> 5] = (double)tot;
    __syncthreads();

    const int bid = blockIdx.x + GXD*(blockIdx.y + GYD*blockIdx.z);
    if (t == 0) {
        double s = 0.0;
#pragma unroll
        for (int i = 0; i < NTHREADS/32; i++) s += wsum[i];
        g_part[bid] = s;
        __threadfence();
        unsigned r = atomicAdd(&g_tick, 1u);
        s_last = (r == NPART - 1);
    }
    __syncthreads();

    // last CTA: fixed-order deterministic final reduction
    if (s_last) {
        __threadfence();
        double s = 0.0;
#pragma unroll
        for (int k = 0; k < NPART/NTHREADS; k++)     // 3 strides, fixed order
            s += g_part[t + k*NTHREADS];
        red[t] = s;
        __syncthreads();
#pragma unroll
        for (int o = NTHREADS/2; o > 0; o >>= 1) {
            if (t < o) red[t] += red[t + o];
            __syncthreads();
        }
        if (t == 0) {
            out[0] = (float)(red[0] / (double)(BB*HH*WW));
            g_tick = 0;                               // reset for next replay
        }
    }
}

// ================= launcher: single kernel =================
extern "C" void kernel_launch(void* const* d_in, const int* in_sizes, int n_in,
                              void* d_out, int out_size) {
    const float* orig = (const float*)d_in[0];   // original_images (2,3,128,128)
    const float* smth = (const float*)d_in[1];   // smooth_images   (2,3,128,128)
    float* out = (float*)d_out;

    const int smem_bytes = 6 * PLANE * (int)sizeof(float);   // 88800 B -> 2 CTAs/SM
    cudaFuncSetAttribute(loss_kernel,
                         cudaFuncAttributeMaxDynamicSharedMemorySize, smem_bytes);

    loss_kernel<<<dim3(GXD, GYD, BB*NSPLIT), NTHREADS, smem_bytes>>>(orig, smth, out);
}